// round 13
// baseline (speedup 1.0000x reference)
#include <cuda_runtime.h>
#include <cuda_fp16.h>
#include <cstdint>
#include <cstddef>

#define BATCH 256
#define SEQ   128
#define DM    1024
#define HS    1024

// fp16 scratch (device globals: allocation-guard-safe)
__device__ __half g_q16[(size_t)BATCH * SEQ * DM];
__device__ __half g_k16[(size_t)BATCH * SEQ * DM];
__device__ __half g_x16[(size_t)BATCH * SEQ * DM];
__device__ __half g_wq16[(size_t)DM * HS];
__device__ __half g_wk16[(size_t)DM * HS];
__device__ __half g_wvT16[(size_t)HS * DM];
__device__ __half g_MT16[(size_t)DM * DM];
__device__ __half g_T16[(size_t)BATCH * SEQ * HS];
__device__ __half g_vT16[(size_t)BATCH * HS * SEQ];

// ===========================================================================
// Helpers
// ===========================================================================
__device__ __forceinline__ uint32_t smem_u32(const void* p) {
    uint32_t a;
    asm("{ .reg .u64 t; cvta.to.shared.u64 t, %1; cvt.u32.u64 %0, t; }"
        : "=r"(a) : "l"(p));
    return a;
}

__device__ __forceinline__ void mma_f16(float* d, const uint32_t* a, const uint32_t* b) {
    asm volatile(
        "mma.sync.aligned.m16n8k16.row.col.f32.f16.f16.f32 "
        "{%0,%1,%2,%3}, {%4,%5,%6,%7}, {%8,%9}, {%0,%1,%2,%3};"
        : "+f"(d[0]), "+f"(d[1]), "+f"(d[2]), "+f"(d[3])
        : "r"(a[0]), "r"(a[1]), "r"(a[2]), "r"(a[3]), "r"(b[0]), "r"(b[1]));
}

__device__ __forceinline__ void ldsm_x4(uint32_t addr, uint32_t& r0, uint32_t& r1,
                                        uint32_t& r2, uint32_t& r3) {
    asm volatile("ldmatrix.sync.aligned.m8n8.x4.shared.b16 {%0,%1,%2,%3}, [%4];"
                 : "=r"(r0), "=r"(r1), "=r"(r2), "=r"(r3) : "r"(addr));
}

__device__ __forceinline__ void cp_async16(uint32_t dst_smem, const void* src) {
    asm volatile("cp.async.cg.shared.global [%0], [%1], 16;"
                 :: "r"(dst_smem), "l"(src));
}
__device__ __forceinline__ void cp_commit() {
    asm volatile("cp.async.commit_group;");
}
template <int N>
__device__ __forceinline__ void cp_wait() {
    asm volatile("cp.async.wait_group %0;" :: "n"(N));
}

// ===========================================================================
// Single fused pre-pass launch. grid (8192, 1, 6), 256 threads.
// ===========================================================================
__global__ __launch_bounds__(256) void prepass(const float* __restrict__ q,
                                               const float* __restrict__ k,
                                               const float* __restrict__ v,
                                               const float* __restrict__ wq,
                                               const float* __restrict__ wk,
                                               const float* __restrict__ wv)
{
    const int z = blockIdx.z;
    if (z < 3) {
        const float* src = (z == 0) ? q : (z == 1) ? k : v;
        __half* dst = (z == 0) ? g_q16 : (z == 1) ? g_k16 : g_x16;
        const size_t i = (size_t)blockIdx.x * 256 + threadIdx.x;
        const size_t stride = 2097152;
        #pragma unroll
        for (int j = 0; j < 4; j++) {
            size_t idx = i + (size_t)j * stride;
            float4 f = reinterpret_cast<const float4*>(src)[idx];
            reinterpret_cast<__half2*>(dst)[idx * 2 + 0] = __float22half2_rn(make_float2(f.x, f.y));
            reinterpret_cast<__half2*>(dst)[idx * 2 + 1] = __float22half2_rn(make_float2(f.z, f.w));
        }
    } else if (z < 5) {
        if (blockIdx.x >= 256) return;
        const float* src = (z == 4) ? wk : wq;
        __half* dst = (z == 4) ? g_wk16 : g_wq16;
        const size_t i = (size_t)blockIdx.x * 256 + threadIdx.x;
        const size_t stride = 65536;
        #pragma unroll
        for (int j = 0; j < 4; j++) {
            size_t idx = i + (size_t)j * stride;
            float4 f = reinterpret_cast<const float4*>(src)[idx];
            reinterpret_cast<__half2*>(dst)[idx * 2 + 0] = __float22half2_rn(make_float2(f.x, f.y));
            reinterpret_cast<__half2*>(dst)[idx * 2 + 1] = __float22half2_rn(make_float2(f.z, f.w));
        }
    } else {
        if (blockIdx.x >= 1024) return;
        __shared__ float t[32][33];
        const int tx = threadIdx.x & 31, ty = threadIdx.x >> 5;
        const int x0 = (blockIdx.x & 31) * 32, y0 = (blockIdx.x >> 5) * 32;
        #pragma unroll
        for (int j = 0; j < 4; j++)
            t[ty + 8 * j][tx] = wv[(size_t)(y0 + ty + 8 * j) * HS + x0 + tx];
        __syncthreads();
        #pragma unroll
        for (int j = 0; j < 4; j++)
            g_wvT16[(size_t)(x0 + ty + 8 * j) * DM + y0 + tx] =
                __float2half_rn(t[tx][ty + 8 * j]);
    }
}

// ===========================================================================
// fp16 NT GEMM: C[m][n] = sum_k A[m][k]*B[n][k].
// CTA 128x128, 128 threads (4 warps), warp tile 64x64.
// BK=32, 3-stage cp.async, one sync per iteration. Pitch 40 hw.
// __launch_bounds__(128, 3): 3 CTAs/SM (12 warps), regs capped at 170.
// ===========================================================================
#define PA 40
#define AST (128 * PA)            // 5120 hw per A stage
#define STG_H (2 * AST)           // 10240 hw per stage (A+B)
#define NST 3
#define GEMM_SMEM (NST * STG_H * 2)   // 61440 B

__device__ __forceinline__ void gemm_nt_f16(const __half* __restrict__ A,
                                            const __half* __restrict__ B,
                                            __half* __restrict__ C,
                                            uint32_t smb,
                                            int m0, int n0, int ldc)
{
    const int tid  = threadIdx.x;
    const int wid  = tid >> 5;
    const int lane = tid & 31;
    const int g    = lane >> 2;
    const int tg   = lane & 3;
    const int wm   = wid >> 1;
    const int wn   = wid & 1;

    const int a_off = (wm * 64 + (lane & 15)) * PA + (lane >> 4) * 8;
    const int b_off = (wn * 64 + ((lane >> 4) << 3) + (lane & 7)) * PA + ((lane >> 3) & 1) * 8;
    const int r0 = tid >> 2, q0 = tid & 3;

    float acc[4][8][4];
    #pragma unroll
    for (int i = 0; i < 4; i++)
        #pragma unroll
        for (int j = 0; j < 8; j++)
            #pragma unroll
            for (int c = 0; c < 4; c++) acc[i][j][c] = 0.f;

    auto load_stage = [&](int ks, int buf) {
        const int k0 = ks * 32;
        const uint32_t sa = smb + (uint32_t)(buf * STG_H) * 2u;
        const uint32_t sb = sa + (uint32_t)AST * 2u;
        #pragma unroll
        for (int l = 0; l < 4; l++) {
            const int r = r0 + l * 32;
            cp_async16(sa + r * 80 + q0 * 16, A + (size_t)(m0 + r) * DM + k0 + q0 * 8);
            cp_async16(sb + r * 80 + q0 * 16, B + (size_t)(n0 + r) * DM + k0 + q0 * 8);
        }
    };

    load_stage(0, 0); cp_commit();
    load_stage(1, 1); cp_commit();

    for (int i = 0; i < 32; i++) {
        cp_wait<1>();
        __syncthreads();
        if (i + 2 < 32) load_stage(i + 2, (i + 2) % NST);
        cp_commit();

        const uint32_t As = smb + (uint32_t)((i % NST) * STG_H) * 2u;
        const uint32_t Bs = As + (uint32_t)AST * 2u;

        #pragma unroll
        for (int j = 0; j < 2; j++) {
            uint32_t a[4][4], bf[8][2];
            #pragma unroll
            for (int mt = 0; mt < 4; mt++)
                ldsm_x4(As + (uint32_t)(a_off + j * 16 + mt * 16 * PA) * 2u,
                        a[mt][0], a[mt][1], a[mt][2], a[mt][3]);
            #pragma unroll
            for (int p = 0; p < 4; p++)
                ldsm_x4(Bs + (uint32_t)(b_off + j * 16 + p * 16 * PA) * 2u,
                        bf[2 * p][0], bf[2 * p][1], bf[2 * p + 1][0], bf[2 * p + 1][1]);
            #pragma unroll
            for (int mt = 0; mt < 4; mt++)
                #pragma unroll
                for (int nt = 0; nt < 8; nt++)
                    mma_f16(acc[mt][nt], a[mt], bf[nt]);
        }
    }

    #pragma unroll
    for (int mt = 0; mt < 4; mt++) {
        const int mrow = m0 + wm * 64 + mt * 16;
        #pragma unroll
        for (int nt = 0; nt < 8; nt++) {
            const int ncol = n0 + wn * 64 + nt * 8 + 2 * tg;
            *reinterpret_cast<__half2*>(C + (size_t)(mrow + g) * ldc + ncol) =
                __float22half2_rn(make_float2(acc[mt][nt][0], acc[mt][nt][1]));
            *reinterpret_cast<__half2*>(C + (size_t)(mrow + g + 8) * ldc + ncol) =
                __float22half2_rn(make_float2(acc[mt][nt][2], acc[mt][nt][3]));
        }
    }
}

__global__ __launch_bounds__(128, 3) void gemm_M()
{
    extern __shared__ __half sm[];
    gemm_nt_f16(g_wk16, g_wq16, g_MT16, smem_u32(sm),
                blockIdx.y * 128, blockIdx.x * 128, DM);
}

__global__ __launch_bounds__(128, 3) void proj_f16()
{
    extern __shared__ __half sm[];
    const uint32_t smb = smem_u32(sm);
    if (blockIdx.z == 0) {
        gemm_nt_f16(g_q16, g_MT16, g_T16, smb,
                    blockIdx.y * 128, blockIdx.x * 128, HS);
    } else {
        gemm_nt_f16(g_wvT16, g_x16 + (size_t)blockIdx.y * SEQ * DM,
                    g_vT16 + (size_t)blockIdx.y * HS * SEQ, smb,
                    blockIdx.x * 128, 0, SEQ);
    }
}

// ===========================================================================
// Attention (R10 layout, unchanged): one CTA per batch, 128 threads (4 warps),
// warp tile 64x64. Phase1 3-stage BK=32, phase3 2-stage BK=16 (PV=24).
// ===========================================================================
#define NSTA 3
#define PP 136
#define PV 24
#define VST (128 * PV)            // 3072 hw per V stage
#define P_HW (NSTA * STG_H)       // 30720
#define ATTN_SMEM ((P_HW + 128 * PP) * 2)   // 96256 B

__global__ __launch_bounds__(128, 2) void attn_f16(float* __restrict__ O)
{
    extern __shared__ __half sm[];
    const uint32_t smb = smem_u32(sm);

    const int tid  = threadIdx.x;
    const int wid  = tid >> 5;
    const int lane = tid & 31;
    const int g    = lane >> 2;
    const int tg   = lane & 3;
    const int wm   = wid >> 1;
    const int wn   = wid & 1;
    const int b    = blockIdx.x;

    const __half* Tb = g_T16 + (size_t)b * SEQ * HS;
    const __half* Kb = g_k16 + (size_t)b * SEQ * DM;
    const __half* Vb = g_vT16 + (size_t)b * HS * SEQ;
    __half* P = sm + P_HW;
    const uint32_t Pu = smb + (uint32_t)P_HW * 2u;

    const int a_off  = (wm * 64 + (lane & 15)) * PA + (lane >> 4) * 8;
    const int b_off  = (wn * 64 + ((lane >> 4) << 3) + (lane & 7)) * PA + ((lane >> 3) & 1) * 8;
    const int bv_off = (wn * 64 + ((lane >> 4) << 3) + (lane & 7)) * PV + ((lane >> 3) & 1) * 8;
    const int p_off  = (wm * 64 + (lane & 15)) * PP + (lane >> 4) * 8;

    const int r0 = tid >> 2, q0 = tid & 3;
    const int vh = tid & 1, vr0 = tid >> 1;

    float acc[4][8][4];
    #pragma unroll
    for (int i = 0; i < 4; i++)
        #pragma unroll
        for (int j = 0; j < 8; j++)
            #pragma unroll
            for (int c = 0; c < 4; c++) acc[i][j][c] = 0.f;

    // ---------------- Phase 1: S = T K^T (BK=32, 3-stage, causal skip) -----
    auto load_s = [&](int ks, int buf) {
        const int k0 = ks * 32;
        const uint32_t sa = smb + (uint32_t)(buf * STG_H) * 2u;
        const uint32_t sb = sa + (uint32_t)AST * 2u;
        #pragma unroll
        for (int l = 0; l < 4; l++) {
            const int r = r0 + l * 32;
            cp_async16(sa + r * 80 + q0 * 16, Tb + (size_t)r * HS + k0 + q0 * 8);
            cp_async16(sb + r * 80 + q0 * 16, Kb + (size_t)r * DM + k0 + q0 * 8);
        }
    };
    auto load_v = [&](int s) {
        const int ntile = s >> 3, ki = s & 7;
        const uint32_t sv = smb + (uint32_t)((s & 1) * VST) * 2u;
        #pragma unroll
        for (int l = 0; l < 2; l++) {
            const int r = vr0 + l * 64;
            cp_async16(sv + r * 48 + vh * 16,
                       Vb + (size_t)(ntile * 128 + r) * SEQ + ki * 16 + vh * 8);
        }
    };

    load_s(0, 0); cp_commit();
    load_s(1, 1); cp_commit();

    for (int i = 0; i < 32; i++) {
        cp_wait<1>();
        __syncthreads();
        if (i + 2 < 32) load_s(i + 2, (i + 2) % NSTA);
        cp_commit();

        const uint32_t As = smb + (uint32_t)((i % NSTA) * STG_H) * 2u;
        const uint32_t Bs = As + (uint32_t)AST * 2u;

        #pragma unroll
        for (int j = 0; j < 2; j++) {
            uint32_t a[4][4], bf[8][2];
            #pragma unroll
            for (int mt = 0; mt < 4; mt++)
                ldsm_x4(As + (uint32_t)(a_off + j * 16 + mt * 16 * PA) * 2u,
                        a[mt][0], a[mt][1], a[mt][2], a[mt][3]);
            #pragma unroll
            for (int p = 0; p < 4; p++)
                ldsm_x4(Bs + (uint32_t)(b_off + j * 16 + p * 16 * PA) * 2u,
                        bf[2 * p][0], bf[2 * p][1], bf[2 * p + 1][0], bf[2 * p + 1][1]);
            #pragma unroll
            for (int mt = 0; mt < 4; mt++)
                #pragma unroll
                for (int nt = 0; nt < 8; nt++)
                    if (wn * 64 + nt * 8 <= wm * 64 + mt * 16 + 15)   // causal skip
                        mma_f16(acc[mt][nt], a[mt], bf[nt]);
        }
    }

    load_v(0); cp_commit();   // prefetch V stage 0, overlaps softmax

    const float scale = 0.03125f;
    #pragma unroll
    for (int mt = 0; mt < 4; mt++) {
        const int mrow = wm * 64 + mt * 16;
        #pragma unroll
        for (int nt = 0; nt < 8; nt++) {
            const int ncol = wn * 64 + nt * 8 + 2 * tg;
            *reinterpret_cast<__half2*>(P + (mrow + g) * PP + ncol) =
                __float22half2_rn(make_float2(acc[mt][nt][0] * scale, acc[mt][nt][1] * scale));
            *reinterpret_cast<__half2*>(P + (mrow + g + 8) * PP + ncol) =
                __float22half2_rn(make_float2(acc[mt][nt][2] * scale, acc[mt][nt][3] * scale));
        }
    }
    __syncthreads();

    // ---------------- Phase 2: causal softmax (warp per row, 32 rows/warp) --
    #pragma unroll 1
    for (int i = 0; i < 32; i++) {
        const int r = wid * 32 + i;
        float x[4];
        #pragma unroll
        for (int j = 0; j < 4; j++) {
            const int col = lane + 32 * j;
            x[j] = (col <= r) ? __half2float(P[r * PP + col]) : -1e30f;
        }
        float m = fmaxf(fmaxf(x[0], x[1]), fmaxf(x[2], x[3]));
        #pragma unroll
        for (int o = 16; o > 0; o >>= 1) m = fmaxf(m, __shfl_xor_sync(0xffffffffu, m, o));
        float e[4], s = 0.f;
        #pragma unroll
        for (int j = 0; j < 4; j++) {
            const int col = lane + 32 * j;
            e[j] = (col <= r) ? __expf(x[j] - m) : 0.f;
            s += e[j];
        }
        #pragma unroll
        for (int o = 16; o > 0; o >>= 1) s += __shfl_xor_sync(0xffffffffu, s, o);
        const float inv = 1.f / s;
        #pragma unroll
        for (int j = 0; j < 4; j++)
            P[r * PP + lane + 32 * j] = __float2half_rn(e[j] * inv);
    }
    __syncthreads();

    // ---------------- Phase 3: O = P * vT (structural-zero skip) -----------
    for (int nt = 0; nt < 8; nt++) {
        #pragma unroll
        for (int i = 0; i < 4; i++)
            #pragma unroll
            for (int j = 0; j < 8; j++)
                #pragma unroll
                for (int c = 0; c < 4; c++) acc[i][j][c] = 0.f;

        for (int ki = 0; ki < 8; ki++) {
            const int s = nt * 8 + ki;
            if (s + 1 < 64) { load_v(s + 1); cp_commit(); cp_wait<1>(); }
            else            { cp_wait<0>(); }
            __syncthreads();
            const uint32_t Vs = smb + (uint32_t)((s & 1) * VST) * 2u;

            const int mt_lo = ki - 4 * wm;
            if (mt_lo <= 3) {
                uint32_t a[4][4], bf[8][2];
                #pragma unroll
                for (int mt = 0; mt < 4; mt++)
                    if (mt >= mt_lo)
                        ldsm_x4(Pu + (uint32_t)(p_off + mt * 16 * PP + ki * 16) * 2u,
                                a[mt][0], a[mt][1], a[mt][2], a[mt][3]);
                #pragma unroll
                for (int p = 0; p < 4; p++)
                    ldsm_x4(Vs + (uint32_t)(bv_off + p * 16 * PV) * 2u,
                            bf[2 * p][0], bf[2 * p][1], bf[2 * p + 1][0], bf[2 * p + 1][1]);
                #pragma unroll
                for (int mt = 0; mt < 4; mt++)
                    if (mt >= mt_lo)
                        #pragma unroll
                        for (int nt2 = 0; nt2 < 8; nt2++)
                            mma_f16(acc[mt][nt2], a[mt], bf[nt2]);
            }
            __syncthreads();
        }

        #pragma unroll
        for (int mt = 0; mt < 4; mt++) {
            const int mrow = wm * 64 + mt * 16;
            #pragma unroll
            for (int nt2 = 0; nt2 < 8; nt2++) {
                const int ncol = nt * 128 + wn * 64 + nt2 * 8 + 2 * tg;
                *reinterpret_cast<float2*>(O + ((size_t)b * SEQ + mrow + g) * HS + ncol) =
                    make_float2(acc[mt][nt2][0], acc[mt][nt2][1]);
                *reinterpret_cast<float2*>(O + ((size_t)b * SEQ + mrow + g + 8) * HS + ncol) =
                    make_float2(acc[mt][nt2][2], acc[mt][nt2][3]);
            }
        }
    }
}

// ===========================================================================
extern "C" void kernel_launch(void* const* d_in, const int* in_sizes, int n_in,
                              void* d_out, int out_size)
{
    const float* query = (const float*)d_in[0];
    const float* key   = (const float*)d_in[1];
    const float* value = (const float*)d_in[2];
    const float* w_q   = (const float*)d_in[3];
    const float* w_k   = (const float*)d_in[4];
    const float* w_v   = (const float*)d_in[5];
    float* out = (float*)d_out;

    prepass<<<dim3(8192, 1, 6), 256>>>(query, key, value, w_q, w_k, w_v);

    cudaFuncSetAttribute(gemm_M, cudaFuncAttributeMaxDynamicSharedMemorySize, GEMM_SMEM);
    gemm_M<<<dim3(8, 8), 128, GEMM_SMEM>>>();

    cudaFuncSetAttribute(proj_f16, cudaFuncAttributeMaxDynamicSharedMemorySize, GEMM_SMEM);
    proj_f16<<<dim3(8, 256, 2), 128, GEMM_SMEM>>>();

    cudaFuncSetAttribute(attn_f16, cudaFuncAttributeMaxDynamicSharedMemorySize, ATTN_SMEM);
    attn_f16<<<BATCH, 128, ATTN_SMEM>>>(out);
}

// round 14
// speedup vs baseline: 1.0844x; 1.0844x over previous
#include <cuda_runtime.h>
#include <cuda_fp16.h>
#include <cstdint>
#include <cstddef>

#define BATCH 256
#define SEQ   128
#define DM    1024
#define HS    1024

// fp16 scratch (device globals: allocation-guard-safe)
__device__ __half g_q16[(size_t)BATCH * SEQ * DM];
__device__ __half g_k16[(size_t)BATCH * SEQ * DM];
__device__ __half g_x16[(size_t)BATCH * SEQ * DM];
__device__ __half g_wq16[(size_t)DM * HS];
__device__ __half g_wk16[(size_t)DM * HS];
__device__ __half g_wvT16[(size_t)HS * DM];
__device__ __half g_MT16[(size_t)DM * DM];
__device__ __half g_T16[(size_t)BATCH * SEQ * HS];
__device__ __half g_vT16[(size_t)BATCH * HS * SEQ];

// ===========================================================================
// Helpers
// ===========================================================================
__device__ __forceinline__ uint32_t smem_u32(const void* p) {
    uint32_t a;
    asm("{ .reg .u64 t; cvta.to.shared.u64 t, %1; cvt.u32.u64 %0, t; }"
        : "=r"(a) : "l"(p));
    return a;
}

__device__ __forceinline__ void mma_f16(float* d, const uint32_t* a, const uint32_t* b) {
    asm volatile(
        "mma.sync.aligned.m16n8k16.row.col.f32.f16.f16.f32 "
        "{%0,%1,%2,%3}, {%4,%5,%6,%7}, {%8,%9}, {%0,%1,%2,%3};"
        : "+f"(d[0]), "+f"(d[1]), "+f"(d[2]), "+f"(d[3])
        : "r"(a[0]), "r"(a[1]), "r"(a[2]), "r"(a[3]), "r"(b[0]), "r"(b[1]));
}

__device__ __forceinline__ void ldsm_x4(uint32_t addr, uint32_t& r0, uint32_t& r1,
                                        uint32_t& r2, uint32_t& r3) {
    asm volatile("ldmatrix.sync.aligned.m8n8.x4.shared.b16 {%0,%1,%2,%3}, [%4];"
                 : "=r"(r0), "=r"(r1), "=r"(r2), "=r"(r3) : "r"(addr));
}

__device__ __forceinline__ void cp_async16(uint32_t dst_smem, const void* src) {
    asm volatile("cp.async.cg.shared.global [%0], [%1], 16;"
                 :: "r"(dst_smem), "l"(src));
}
__device__ __forceinline__ void cp_commit() {
    asm volatile("cp.async.commit_group;");
}
template <int N>
__device__ __forceinline__ void cp_wait() {
    asm volatile("cp.async.wait_group %0;" :: "n"(N));
}

// ===========================================================================
// Single fused pre-pass launch. grid (8192, 1, 6), 256 threads.
// ===========================================================================
__global__ __launch_bounds__(256) void prepass(const float* __restrict__ q,
                                               const float* __restrict__ k,
                                               const float* __restrict__ v,
                                               const float* __restrict__ wq,
                                               const float* __restrict__ wk,
                                               const float* __restrict__ wv)
{
    const int z = blockIdx.z;
    if (z < 3) {
        const float* src = (z == 0) ? q : (z == 1) ? k : v;
        __half* dst = (z == 0) ? g_q16 : (z == 1) ? g_k16 : g_x16;
        const size_t i = (size_t)blockIdx.x * 256 + threadIdx.x;
        const size_t stride = 2097152;
        #pragma unroll
        for (int j = 0; j < 4; j++) {
            size_t idx = i + (size_t)j * stride;
            float4 f = reinterpret_cast<const float4*>(src)[idx];
            reinterpret_cast<__half2*>(dst)[idx * 2 + 0] = __float22half2_rn(make_float2(f.x, f.y));
            reinterpret_cast<__half2*>(dst)[idx * 2 + 1] = __float22half2_rn(make_float2(f.z, f.w));
        }
    } else if (z < 5) {
        if (blockIdx.x >= 256) return;
        const float* src = (z == 4) ? wk : wq;
        __half* dst = (z == 4) ? g_wk16 : g_wq16;
        const size_t i = (size_t)blockIdx.x * 256 + threadIdx.x;
        const size_t stride = 65536;
        #pragma unroll
        for (int j = 0; j < 4; j++) {
            size_t idx = i + (size_t)j * stride;
            float4 f = reinterpret_cast<const float4*>(src)[idx];
            reinterpret_cast<__half2*>(dst)[idx * 2 + 0] = __float22half2_rn(make_float2(f.x, f.y));
            reinterpret_cast<__half2*>(dst)[idx * 2 + 1] = __float22half2_rn(make_float2(f.z, f.w));
        }
    } else {
        if (blockIdx.x >= 1024) return;
        __shared__ float t[32][33];
        const int tx = threadIdx.x & 31, ty = threadIdx.x >> 5;
        const int x0 = (blockIdx.x & 31) * 32, y0 = (blockIdx.x >> 5) * 32;
        #pragma unroll
        for (int j = 0; j < 4; j++)
            t[ty + 8 * j][tx] = wv[(size_t)(y0 + ty + 8 * j) * HS + x0 + tx];
        __syncthreads();
        #pragma unroll
        for (int j = 0; j < 4; j++)
            g_wvT16[(size_t)(x0 + ty + 8 * j) * DM + y0 + tx] =
                __float2half_rn(t[tx][ty + 8 * j]);
    }
}

// ===========================================================================
// fp16 NT GEMM (R10/R12 proven config): C[m][n] = sum_k A[m][k]*B[n][k].
// CTA 128x128, 128 threads (4 warps), warp tile 64x64.
// BK=32, 3-stage cp.async, one sync per iteration. Pitch 40 hw. 2 CTAs/SM.
// ===========================================================================
#define PA 40
#define AST (128 * PA)            // 5120 hw per A stage
#define STG_H (2 * AST)           // 10240 hw per stage (A+B)
#define NST 3
#define GEMM_SMEM (NST * STG_H * 2)   // 61440 B

__device__ __forceinline__ void gemm_nt_f16(const __half* __restrict__ A,
                                            const __half* __restrict__ B,
                                            __half* __restrict__ C,
                                            uint32_t smb,
                                            int m0, int n0, int ldc)
{
    const int tid  = threadIdx.x;
    const int wid  = tid >> 5;
    const int lane = tid & 31;
    const int g    = lane >> 2;
    const int tg   = lane & 3;
    const int wm   = wid >> 1;
    const int wn   = wid & 1;

    const int a_off = (wm * 64 + (lane & 15)) * PA + (lane >> 4) * 8;
    const int b_off = (wn * 64 + ((lane >> 4) << 3) + (lane & 7)) * PA + ((lane >> 3) & 1) * 8;
    const int r0 = tid >> 2, q0 = tid & 3;

    float acc[4][8][4];
    #pragma unroll
    for (int i = 0; i < 4; i++)
        #pragma unroll
        for (int j = 0; j < 8; j++)
            #pragma unroll
            for (int c = 0; c < 4; c++) acc[i][j][c] = 0.f;

    auto load_stage = [&](int ks, int buf) {
        const int k0 = ks * 32;
        const uint32_t sa = smb + (uint32_t)(buf * STG_H) * 2u;
        const uint32_t sb = sa + (uint32_t)AST * 2u;
        #pragma unroll
        for (int l = 0; l < 4; l++) {
            const int r = r0 + l * 32;
            cp_async16(sa + r * 80 + q0 * 16, A + (size_t)(m0 + r) * DM + k0 + q0 * 8);
            cp_async16(sb + r * 80 + q0 * 16, B + (size_t)(n0 + r) * DM + k0 + q0 * 8);
        }
    };

    load_stage(0, 0); cp_commit();
    load_stage(1, 1); cp_commit();

    for (int i = 0; i < 32; i++) {
        cp_wait<1>();
        __syncthreads();
        if (i + 2 < 32) load_stage(i + 2, (i + 2) % NST);
        cp_commit();

        const uint32_t As = smb + (uint32_t)((i % NST) * STG_H) * 2u;
        const uint32_t Bs = As + (uint32_t)AST * 2u;

        #pragma unroll
        for (int j = 0; j < 2; j++) {
            uint32_t a[4][4], bf[8][2];
            #pragma unroll
            for (int mt = 0; mt < 4; mt++)
                ldsm_x4(As + (uint32_t)(a_off + j * 16 + mt * 16 * PA) * 2u,
                        a[mt][0], a[mt][1], a[mt][2], a[mt][3]);
            #pragma unroll
            for (int p = 0; p < 4; p++)
                ldsm_x4(Bs + (uint32_t)(b_off + j * 16 + p * 16 * PA) * 2u,
                        bf[2 * p][0], bf[2 * p][1], bf[2 * p + 1][0], bf[2 * p + 1][1]);
            #pragma unroll
            for (int mt = 0; mt < 4; mt++)
                #pragma unroll
                for (int nt = 0; nt < 8; nt++)
                    mma_f16(acc[mt][nt], a[mt], bf[nt]);
        }
    }

    #pragma unroll
    for (int mt = 0; mt < 4; mt++) {
        const int mrow = m0 + wm * 64 + mt * 16;
        #pragma unroll
        for (int nt = 0; nt < 8; nt++) {
            const int ncol = n0 + wn * 64 + nt * 8 + 2 * tg;
            *reinterpret_cast<__half2*>(C + (size_t)(mrow + g) * ldc + ncol) =
                __float22half2_rn(make_float2(acc[mt][nt][0], acc[mt][nt][1]));
            *reinterpret_cast<__half2*>(C + (size_t)(mrow + g + 8) * ldc + ncol) =
                __float22half2_rn(make_float2(acc[mt][nt][2], acc[mt][nt][3]));
        }
    }
}

__global__ __launch_bounds__(128, 2) void gemm_M()
{
    extern __shared__ __half sm[];
    gemm_nt_f16(g_wk16, g_wq16, g_MT16, smem_u32(sm),
                blockIdx.y * 128, blockIdx.x * 128, DM);
}

__global__ __launch_bounds__(128, 2) void proj_f16()
{
    extern __shared__ __half sm[];
    const uint32_t smb = smem_u32(sm);
    if (blockIdx.z == 0) {
        gemm_nt_f16(g_q16, g_MT16, g_T16, smb,
                    blockIdx.y * 128, blockIdx.x * 128, HS);
    } else {
        gemm_nt_f16(g_wvT16, g_x16 + (size_t)blockIdx.y * SEQ * DM,
                    g_vT16 + (size_t)blockIdx.y * HS * SEQ, smb,
                    blockIdx.x * 128, 0, SEQ);
    }
}

// ===========================================================================
// Attention: one CTA per batch, 128 threads (4 warps).
// INTERLEAVED row tiles: warp wm owns row-tiles {wm, wm+2, wm+4, wm+6}
// (rows 16*(wm+2*mt)) -> balanced causal work across warps in both phases.
// Phase1 3-stage BK=32; phase3 2-stage BK=16 (PV=24).
// ===========================================================================
#define NSTA 3
#define PP 136
#define PV 24
#define VST (128 * PV)            // 3072 hw per V stage
#define P_HW (NSTA * STG_H)       // 30720
#define ATTN_SMEM ((P_HW + 128 * PP) * 2)   // 96256 B

__global__ __launch_bounds__(128, 2) void attn_f16(float* __restrict__ O)
{
    extern __shared__ __half sm[];
    const uint32_t smb = smem_u32(sm);

    const int tid  = threadIdx.x;
    const int wid  = tid >> 5;
    const int lane = tid & 31;
    const int g    = lane >> 2;
    const int tg   = lane & 3;
    const int wm   = wid >> 1;
    const int wn   = wid & 1;
    const int b    = blockIdx.x;

    const __half* Tb = g_T16 + (size_t)b * SEQ * HS;
    const __half* Kb = g_k16 + (size_t)b * SEQ * DM;
    const __half* Vb = g_vT16 + (size_t)b * HS * SEQ;
    __half* P = sm + P_HW;
    const uint32_t Pu = smb + (uint32_t)P_HW * 2u;

    // interleaved row-tile bases: row_base(mt) = 16*(wm + 2*mt)
    const int a_lane = (lane & 15) * PA + (lane >> 4) * 8;
    const int p_lane = (lane & 15) * PP + (lane >> 4) * 8;
    const int b_off  = (wn * 64 + ((lane >> 4) << 3) + (lane & 7)) * PA + ((lane >> 3) & 1) * 8;
    const int bv_off = (wn * 64 + ((lane >> 4) << 3) + (lane & 7)) * PV + ((lane >> 3) & 1) * 8;

    const int r0 = tid >> 2, q0 = tid & 3;
    const int vh = tid & 1, vr0 = tid >> 1;

    float acc[4][8][4];
    #pragma unroll
    for (int i = 0; i < 4; i++)
        #pragma unroll
        for (int j = 0; j < 8; j++)
            #pragma unroll
            for (int c = 0; c < 4; c++) acc[i][j][c] = 0.f;

    // ---------------- Phase 1: S = T K^T (BK=32, 3-stage, balanced skip) ---
    auto load_s = [&](int ks, int buf) {
        const int k0 = ks * 32;
        const uint32_t sa = smb + (uint32_t)(buf * STG_H) * 2u;
        const uint32_t sb = sa + (uint32_t)AST * 2u;
        #pragma unroll
        for (int l = 0; l < 4; l++) {
            const int r = r0 + l * 32;
            cp_async16(sa + r * 80 + q0 * 16, Tb + (size_t)r * HS + k0 + q0 * 8);
            cp_async16(sb + r * 80 + q0 * 16, Kb + (size_t)r * DM + k0 + q0 * 8);
        }
    };
    auto load_v = [&](int s) {
        const int ntile = s >> 3, ki = s & 7;
        const uint32_t sv = smb + (uint32_t)((s & 1) * VST) * 2u;
        #pragma unroll
        for (int l = 0; l < 2; l++) {
            const int r = vr0 + l * 64;
            cp_async16(sv + r * 48 + vh * 16,
                       Vb + (size_t)(ntile * 128 + r) * SEQ + ki * 16 + vh * 8);
        }
    };

    load_s(0, 0); cp_commit();
    load_s(1, 1); cp_commit();

    for (int i = 0; i < 32; i++) {
        cp_wait<1>();
        __syncthreads();
        if (i + 2 < 32) load_s(i + 2, (i + 2) % NSTA);
        cp_commit();

        const uint32_t As = smb + (uint32_t)((i % NSTA) * STG_H) * 2u;
        const uint32_t Bs = As + (uint32_t)AST * 2u;

        #pragma unroll
        for (int j = 0; j < 2; j++) {
            uint32_t a[4][4], bf[8][2];
            #pragma unroll
            for (int mt = 0; mt < 4; mt++)
                ldsm_x4(As + (uint32_t)(a_lane + j * 16 + 16 * (wm + 2 * mt) * PA) * 2u,
                        a[mt][0], a[mt][1], a[mt][2], a[mt][3]);
            #pragma unroll
            for (int p = 0; p < 4; p++)
                ldsm_x4(Bs + (uint32_t)(b_off + j * 16 + p * 16 * PA) * 2u,
                        bf[2 * p][0], bf[2 * p][1], bf[2 * p + 1][0], bf[2 * p + 1][1]);
            #pragma unroll
            for (int mt = 0; mt < 4; mt++)
                #pragma unroll
                for (int nt = 0; nt < 8; nt++)
                    if (wn * 64 + nt * 8 <= 16 * (wm + 2 * mt) + 15)   // causal skip
                        mma_f16(acc[mt][nt], a[mt], bf[nt]);
        }
    }

    load_v(0); cp_commit();   // prefetch V stage 0, overlaps softmax

    const float scale = 0.03125f;
    #pragma unroll
    for (int mt = 0; mt < 4; mt++) {
        const int mrow = 16 * (wm + 2 * mt);
        #pragma unroll
        for (int nt = 0; nt < 8; nt++) {
            const int ncol = wn * 64 + nt * 8 + 2 * tg;
            *reinterpret_cast<__half2*>(P + (mrow + g) * PP + ncol) =
                __float22half2_rn(make_float2(acc[mt][nt][0] * scale, acc[mt][nt][1] * scale));
            *reinterpret_cast<__half2*>(P + (mrow + g + 8) * PP + ncol) =
                __float22half2_rn(make_float2(acc[mt][nt][2] * scale, acc[mt][nt][3] * scale));
        }
    }
    __syncthreads();

    // ---------------- Phase 2: causal softmax (warp per row, 32 rows/warp) --
    #pragma unroll 1
    for (int i = 0; i < 32; i++) {
        const int r = wid * 32 + i;
        float x[4];
        #pragma unroll
        for (int j = 0; j < 4; j++) {
            const int col = lane + 32 * j;
            x[j] = (col <= r) ? __half2float(P[r * PP + col]) : -1e30f;
        }
        float m = fmaxf(fmaxf(x[0], x[1]), fmaxf(x[2], x[3]));
        #pragma unroll
        for (int o = 16; o > 0; o >>= 1) m = fmaxf(m, __shfl_xor_sync(0xffffffffu, m, o));
        float e[4], s = 0.f;
        #pragma unroll
        for (int j = 0; j < 4; j++) {
            const int col = lane + 32 * j;
            e[j] = (col <= r) ? __expf(x[j] - m) : 0.f;
            s += e[j];
        }
        #pragma unroll
        for (int o = 16; o > 0; o >>= 1) s += __shfl_xor_sync(0xffffffffu, s, o);
        const float inv = 1.f / s;
        #pragma unroll
        for (int j = 0; j < 4; j++)
            P[r * PP + lane + 32 * j] = __float2half_rn(e[j] * inv);
    }
    __syncthreads();

    // ---------------- Phase 3: O = P * vT (balanced structural-zero skip) --
    // chunk ki active for tile mt iff ki <= wm + 2*mt  ->  mt_lo = (ki-wm+1)>>1
    for (int nt = 0; nt < 8; nt++) {
        #pragma unroll
        for (int i = 0; i < 4; i++)
            #pragma unroll
            for (int j = 0; j < 8; j++)
                #pragma unroll
                for (int c = 0; c < 4; c++) acc[i][j][c] = 0.f;

        for (int ki = 0; ki < 8; ki++) {
            const int s = nt * 8 + ki;
            if (s + 1 < 64) { load_v(s + 1); cp_commit(); cp_wait<1>(); }
            else            { cp_wait<0>(); }
            __syncthreads();
            const uint32_t Vs = smb + (uint32_t)((s & 1) * VST) * 2u;

            const int mt_lo = (ki - wm + 1) >> 1;
            if (mt_lo <= 3) {
                uint32_t a[4][4], bf[8][2];
                #pragma unroll
                for (int mt = 0; mt < 4; mt++)
                    if (mt >= mt_lo)
                        ldsm_x4(Pu + (uint32_t)(p_lane + 16 * (wm + 2 * mt) * PP + ki * 16) * 2u,
                                a[mt][0], a[mt][1], a[mt][2], a[mt][3]);
                #pragma unroll
                for (int p = 0; p < 4; p++)
                    ldsm_x4(Vs + (uint32_t)(bv_off + p * 16 * PV) * 2u,
                            bf[2 * p][0], bf[2 * p][1], bf[2 * p + 1][0], bf[2 * p + 1][1]);
                #pragma unroll
                for (int mt = 0; mt < 4; mt++)
                    if (mt >= mt_lo)
                        #pragma unroll
                        for (int nt2 = 0; nt2 < 8; nt2++)
                            mma_f16(acc[mt][nt2], a[mt], bf[nt2]);
            }
            __syncthreads();
        }

        #pragma unroll
        for (int mt = 0; mt < 4; mt++) {
            const int mrow = 16 * (wm + 2 * mt);
            #pragma unroll
            for (int nt2 = 0; nt2 < 8; nt2++) {
                const int ncol = nt * 128 + wn * 64 + nt2 * 8 + 2 * tg;
                *reinterpret_cast<float2*>(O + ((size_t)b * SEQ + mrow + g) * HS + ncol) =
                    make_float2(acc[mt][nt2][0], acc[mt][nt2][1]);
                *reinterpret_cast<float2*>(O + ((size_t)b * SEQ + mrow + g + 8) * HS + ncol) =
                    make_float2(acc[mt][nt2][2], acc[mt][nt2][3]);
            }
        }
    }
}

// ===========================================================================
extern "C" void kernel_launch(void* const* d_in, const int* in_sizes, int n_in,
                              void* d_out, int out_size)
{
    const float* query = (const float*)d_in[0];
    const float* key   = (const float*)d_in[1];
    const float* value = (const float*)d_in[2];
    const float* w_q   = (const float*)d_in[3];
    const float* w_k   = (const float*)d_in[4];
    const float* w_v   = (const float*)d_in[5];
    float* out = (float*)d_out;

    prepass<<<dim3(8192, 1, 6), 256>>>(query, key, value, w_q, w_k, w_v);

    cudaFuncSetAttribute(gemm_M, cudaFuncAttributeMaxDynamicSharedMemorySize, GEMM_SMEM);
    gemm_M<<<dim3(8, 8), 128, GEMM_SMEM>>>();

    cudaFuncSetAttribute(proj_f16, cudaFuncAttributeMaxDynamicSharedMemorySize, GEMM_SMEM);
    proj_f16<<<dim3(8, 256, 2), 128, GEMM_SMEM>>>();

    cudaFuncSetAttribute(attn_f16, cudaFuncAttributeMaxDynamicSharedMemorySize, ATTN_SMEM);
    attn_f16<<<BATCH, 128, ATTN_SMEM>>>(out);
}